// round 1
// baseline (speedup 1.0000x reference)
#include <cuda_runtime.h>

// RelationalCritic: B=2048, N=32, F=64, E=8, H=128, NA=4, NACT=16
#define Bn 2048
#define Nn 32
#define Fn 64
#define En 8
#define Hn 128
#define NAn 4
#define NACTn 16
#define Kc 1152  // E*H + H  (stacked [Wrel; Wroot] contraction dim)

// Scratch (device globals; no allocations allowed).
// g_yx[row = b*32+j][k]: k in [0,1024) = y[e,d] (e=k>>7,d=k&127), k in [1024,1152) = x[j,d]
__device__ float g_yx[(size_t)Bn * Nn * Kc];
__device__ float g_pooled[(size_t)Bn * Hn];

// ---------------------------------------------------------------------------
// K1: fused embed + adjacency-normalized aggregation. One block per batch b.
//   x[j,:] = unary[b,j,:] @ We + be             (smem)
//   adj[e][j] = bitmask over i of binary[b,i,j,e]
//   y[e,j,:] = (1/deg) * sum_{i in mask} x[i,:]
// Writes y into g_yx cols [0,1024) and x into cols [1024,1152).
// ---------------------------------------------------------------------------
__global__ __launch_bounds__(256) void k_embed_y(
    const float* __restrict__ unary, const int* __restrict__ binary,
    const float* __restrict__ We, const float* __restrict__ be)
{
    extern __shared__ float sm[];
    float* sWe = sm;                    // 64*128
    float* sU  = sm + 8192;             // 32*64
    float* sX  = sm + 8192 + 2048;      // 32*128
    unsigned* adj = (unsigned*)(sm + 8192 + 2048 + 4096);  // [e*32+j]

    const int b = blockIdx.x, t = threadIdx.x;

    // cooperative loads (float4, coalesced)
    const float4* We4 = (const float4*)We;
    for (int i = t; i < 2048; i += 256) ((float4*)sWe)[i] = We4[i];
    const float4* U4 = (const float4*)(unary + (size_t)b * Nn * Fn);
    for (int i = t; i < 512; i += 256) ((float4*)sU)[i] = U4[i];

    // adjacency bitmasks: thread t <-> (j = t>>3, e = t&7); address i*256 + t is
    // fully coalesced across the warp for each i.
    {
        const int* bb = binary + (size_t)b * Nn * Nn * En;
        unsigned m = 0;
        #pragma unroll
        for (int i = 0; i < 32; i++)
            m |= ((unsigned)(bb[i * 256 + t] != 0)) << i;
        adj[(t & 7) * 32 + (t >> 3)] = m;
    }
    __syncthreads();

    // embed: thread computes 16 outputs (j = t>>3, h0 = (t&7)*16)
    {
        const int j = t >> 3, h0 = (t & 7) * 16;
        float acc[16];
        #pragma unroll
        for (int q = 0; q < 16; q++) acc[q] = be[h0 + q];
        #pragma unroll 8
        for (int k = 0; k < 64; k++) {
            const float u = sU[j * 64 + k];
            const float* wr = sWe + k * 128 + h0;
            #pragma unroll
            for (int q = 0; q < 16; q++) acc[q] = fmaf(u, wr[q], acc[q]);
        }
        float* xs = sX + j * 128 + h0;
        float* xg = g_yx + (size_t)(b * 32 + j) * Kc + 1024 + h0;
        #pragma unroll
        for (int q = 0; q < 16; q++) xs[q] = acc[q];
        #pragma unroll
        for (int q = 0; q < 16; q += 4)
            *(float4*)(xg + q) = make_float4(acc[q], acc[q+1], acc[q+2], acc[q+3]);
    }
    __syncthreads();

    // y: one warp per (e,j) pair; lane owns 4 consecutive d (conflict-free LDS.128,
    // fully coalesced STG.128).
    const int w = t >> 5, lane = t & 31;
    const float4* sX4 = (const float4*)sX;   // [i][32] float4
    for (int p = w; p < 256; p += 8) {
        const int e = p >> 5, j = p & 31;
        const unsigned m = adj[e * 32 + j];
        const float inv = m ? 1.0f / (float)__popc(m) : 0.0f;
        float ax = 0.f, ay = 0.f, az = 0.f, aw = 0.f;
        unsigned mm = m;
        while (mm) {
            const int i = __ffs(mm) - 1; mm &= mm - 1;
            const float4 v = sX4[i * 32 + lane];
            ax += v.x; ay += v.y; az += v.z; aw += v.w;
        }
        ((float4*)(g_yx + (size_t)(b * 32 + j) * Kc + e * 128))[lane] =
            make_float4(ax * inv, ay * inv, az * inv, aw * inv);
    }
}

// ---------------------------------------------------------------------------
// K2: big GEMM  h[b*32+j][h] = sum_k yx[row][k] * Wcat[k][h]  (+brel, relu)
// then max-pool over the 32 nodes of the batch -> g_pooled[b][h].
// Wcat rows [0,1024) = Wrel flattened, rows [1024,1152) = Wroot (no repack).
// Block = one batch (M=32, N=128, K=1152), 256 threads, 4x4 microtile.
// ---------------------------------------------------------------------------
__global__ __launch_bounds__(256) void k_gemm_pool(
    const float* __restrict__ Wrel, const float* __restrict__ Wroot,
    const float* __restrict__ brel)
{
    __shared__ float As[32][36];    // [kk][j] (padded)
    __shared__ float Bs[32 * 128];  // [kk][h]
    __shared__ float red[8][128];

    const int b = blockIdx.x, t = threadIdx.x;
    const int tx = t & 31, ty = t >> 5;     // h0 = tx*4, j0 = ty*4
    float acc[4][4] = {};

    const float* Arow = g_yx + (size_t)b * 32 * Kc;
    const int jl = t >> 3, kk0 = (t & 7) * 4;

    for (int k0 = 0; k0 < Kc; k0 += 32) {
        // stage to registers
        const float4 av = *(const float4*)(Arow + (size_t)jl * Kc + k0 + kk0);
        const float* Bsrc = (k0 < 1024) ? (Wrel + (size_t)k0 * 128)
                                        : (Wroot + (size_t)(k0 - 1024) * 128);
        const float4 bv0 = ((const float4*)Bsrc)[t];
        const float4 bv1 = ((const float4*)Bsrc)[t + 256];
        const float4 bv2 = ((const float4*)Bsrc)[t + 512];
        const float4 bv3 = ((const float4*)Bsrc)[t + 768];
        __syncthreads();   // previous tile fully consumed
        As[kk0 + 0][jl] = av.x; As[kk0 + 1][jl] = av.y;
        As[kk0 + 2][jl] = av.z; As[kk0 + 3][jl] = av.w;
        ((float4*)Bs)[t]       = bv0;
        ((float4*)Bs)[t + 256] = bv1;
        ((float4*)Bs)[t + 512] = bv2;
        ((float4*)Bs)[t + 768] = bv3;
        __syncthreads();

        #pragma unroll
        for (int kk = 0; kk < 32; kk++) {
            const float a0 = As[kk][ty * 4 + 0];
            const float a1 = As[kk][ty * 4 + 1];
            const float a2 = As[kk][ty * 4 + 2];
            const float a3 = As[kk][ty * 4 + 3];
            const float4 bv = *(const float4*)(Bs + kk * 128 + tx * 4);
            acc[0][0] = fmaf(a0, bv.x, acc[0][0]); acc[0][1] = fmaf(a0, bv.y, acc[0][1]);
            acc[0][2] = fmaf(a0, bv.z, acc[0][2]); acc[0][3] = fmaf(a0, bv.w, acc[0][3]);
            acc[1][0] = fmaf(a1, bv.x, acc[1][0]); acc[1][1] = fmaf(a1, bv.y, acc[1][1]);
            acc[1][2] = fmaf(a1, bv.z, acc[1][2]); acc[1][3] = fmaf(a1, bv.w, acc[1][3]);
            acc[2][0] = fmaf(a2, bv.x, acc[2][0]); acc[2][1] = fmaf(a2, bv.y, acc[2][1]);
            acc[2][2] = fmaf(a2, bv.z, acc[2][2]); acc[2][3] = fmaf(a2, bv.w, acc[2][3]);
            acc[3][0] = fmaf(a3, bv.x, acc[3][0]); acc[3][1] = fmaf(a3, bv.y, acc[3][1]);
            acc[3][2] = fmaf(a3, bv.z, acc[3][2]); acc[3][3] = fmaf(a3, bv.w, acc[3][3]);
        }
    }

    // epilogue: +brel, relu, max over this thread's 4 j rows
    const float4 bias = *(const float4*)(brel + tx * 4);
    float mx0 = 0.f, mx1 = 0.f, mx2 = 0.f, mx3 = 0.f;  // relu output >= 0
    #pragma unroll
    for (int jq = 0; jq < 4; jq++) {
        mx0 = fmaxf(mx0, acc[jq][0] + bias.x);
        mx1 = fmaxf(mx1, acc[jq][1] + bias.y);
        mx2 = fmaxf(mx2, acc[jq][2] + bias.z);
        mx3 = fmaxf(mx3, acc[jq][3] + bias.w);
    }
    *(float4*)&red[ty][tx * 4] = make_float4(mx0, mx1, mx2, mx3);
    __syncthreads();
    if (t < 128) {
        float m = red[0][t];
        #pragma unroll
        for (int r = 1; r < 8; r++) m = fmaxf(m, red[r][t]);
        g_pooled[(size_t)b * 128 + t] = m;
    }
}

// ---------------------------------------------------------------------------
// K3: per-agent heads + action gather.
// Block = (agent a, group of 32 batches); W1[a]/W2[a] cached in smem.
// Only the argmax-selected column of W2 is computed.
// ---------------------------------------------------------------------------
__global__ __launch_bounds__(128) void k_heads(
    const float* __restrict__ actions, const float* __restrict__ W1,
    const float* __restrict__ b1, const float* __restrict__ W2,
    const float* __restrict__ b2, float* __restrict__ out)
{
    extern __shared__ float sm[];
    float* sW1 = sm;                  // 128*128
    float* sW2 = sm + 16384;          // 128*16
    float* sP  = sm + 16384 + 2048;   // 32*128
    __shared__ float sred[4];

    const int a = blockIdx.x >> 6, bg = blockIdx.x & 63, t = threadIdx.x;

    const float4* w14 = (const float4*)(W1 + (size_t)a * 16384);
    for (int i = t; i < 4096; i += 128) ((float4*)sW1)[i] = w14[i];
    const float4* w24 = (const float4*)(W2 + (size_t)a * 2048);
    for (int i = t; i < 512; i += 128) ((float4*)sW2)[i] = w24[i];
    const float4* p4 = (const float4*)(g_pooled + (size_t)bg * 32 * 128);
    for (int i = t; i < 1024; i += 128) ((float4*)sP)[i] = p4[i];
    const float bias1 = b1[a * 128 + t];
    __syncthreads();

    for (int bb = 0; bb < 32; bb++) {
        const int bidx = bg * 32 + bb;
        float z = bias1;
        const float* pr = sP + bb * 128;
        #pragma unroll 16
        for (int d = 0; d < 128; d++)
            z = fmaf(pr[d], sW1[d * 128 + t], z);
        z = z > 0.f ? z : 0.01f * z;  // LeakyReLU

        // argmax over 16 actions (first occurrence, like jnp.argmax)
        const float* ac = actions + ((size_t)a * Bn + bidx) * 16;
        int k = 0; float best = ac[0];
        #pragma unroll
        for (int q = 1; q < 16; q++) {
            const float v = ac[q];
            if (v > best) { best = v; k = q; }
        }

        float part = z * sW2[t * 16 + k];
        #pragma unroll
        for (int off = 16; off; off >>= 1)
            part += __shfl_xor_sync(0xffffffffu, part, off);
        if ((t & 31) == 0) sred[t >> 5] = part;
        __syncthreads();
        if (t == 0)
            out[(size_t)a * Bn + bidx] =
                sred[0] + sred[1] + sred[2] + sred[3] + b2[a * 16 + k];
        __syncthreads();
    }
}

// ---------------------------------------------------------------------------
extern "C" void kernel_launch(void* const* d_in, const int* in_sizes, int n_in,
                              void* d_out, int out_size)
{
    const float* unary   = (const float*)d_in[0];
    const int*   binary  = (const int*)  d_in[1];
    const float* actions = (const float*)d_in[2];
    const float* We      = (const float*)d_in[3];
    const float* be      = (const float*)d_in[4];
    const float* Wrel    = (const float*)d_in[5];
    const float* Wroot   = (const float*)d_in[6];
    const float* brel    = (const float*)d_in[7];
    const float* W1      = (const float*)d_in[8];
    const float* b1      = (const float*)d_in[9];
    const float* W2      = (const float*)d_in[10];
    const float* b2      = (const float*)d_in[11];
    float* out = (float*)d_out;

    const int smem_k1 = (8192 + 2048 + 4096) * 4 + 256 * 4;       // 58368 B
    const int smem_k3 = (16384 + 2048 + 4096) * 4;                // 90112 B
    cudaFuncSetAttribute(k_embed_y, cudaFuncAttributeMaxDynamicSharedMemorySize, smem_k1);
    cudaFuncSetAttribute(k_heads,   cudaFuncAttributeMaxDynamicSharedMemorySize, smem_k3);

    k_embed_y<<<Bn, 256, smem_k1>>>(unary, binary, We, be);
    k_gemm_pool<<<Bn, 256>>>(Wrel, Wroot, brel);
    k_heads<<<NAn * 64, 128, smem_k3>>>(actions, W1, b1, W2, b2, out);
}